// round 1
// baseline (speedup 1.0000x reference)
#include <cuda_runtime.h>

#define NB 8
#define NC 256
#define HW 4096
#define DH 128
#define NO 256

// Scratch: qk projection result, layout [b][o][n] (n contiguous).
// o in [0,128) = q (pre-scaled), o in [128,256) = k.
__device__ float g_QK[(size_t)NB * NO * HW];

// ---------------------------------------------------------------------------
// Kernel 1: g_QK[b][o][n] = sum_c W[o][c] * x[b][c][n]   (q rows pre-scaled)
// 64x64 block tile, k-tile 32, 256 threads, 4x4 micro-tile.
// ---------------------------------------------------------------------------
__global__ __launch_bounds__(256) void proj_kernel(const float* __restrict__ x,
                                                   const float* __restrict__ W) {
    __shared__ float As[32][64];   // [k][o]
    __shared__ float Bs[32][64];   // [k][n]
    const int n0 = blockIdx.x * 64;
    const int o0 = blockIdx.y * 64;
    const int b  = blockIdx.z;
    const int tid = threadIdx.x;
    const int tx = tid & 15;
    const int ty = tid >> 4;
    const float* xb = x + (size_t)b * NC * HW;

    float acc[4][4] = {};
    for (int k0 = 0; k0 < NC; k0 += 32) {
        __syncthreads();
        // A tile: W[o0+row][k0+..], 64 rows x 32, transpose into As[k][o]
        #pragma unroll
        for (int i = 0; i < 2; i++) {
            int f = tid + i * 256;   // 512 float4 total
            int row = f >> 3;        // 8 float4 per row
            int c4  = f & 7;
            float4 v = *(const float4*)(W + (size_t)(o0 + row) * NC + k0 + c4 * 4);
            As[c4 * 4 + 0][row] = v.x;
            As[c4 * 4 + 1][row] = v.y;
            As[c4 * 4 + 2][row] = v.z;
            As[c4 * 4 + 3][row] = v.w;
        }
        // B tile: x[b][k0+row][n0+..], 32 rows x 64, direct
        #pragma unroll
        for (int i = 0; i < 2; i++) {
            int f = tid + i * 256;
            int row = f >> 4;        // 16 float4 per row
            int c4  = f & 15;
            *(float4*)&Bs[row][c4 * 4] =
                *(const float4*)(xb + (size_t)(k0 + row) * HW + n0 + c4 * 4);
        }
        __syncthreads();
        #pragma unroll
        for (int k = 0; k < 32; k++) {
            float a[4], bb[4];
            *(float4*)a  = *(const float4*)&As[k][ty * 4];
            *(float4*)bb = *(const float4*)&Bs[k][tx * 4];
            #pragma unroll
            for (int r = 0; r < 4; r++)
                #pragma unroll
                for (int c = 0; c < 4; c++)
                    acc[r][c] = fmaf(a[r], bb[c], acc[r][c]);
        }
    }
    const float SCALE = 0.088388347648318447f;  // 128^-0.5
    #pragma unroll
    for (int r = 0; r < 4; r++) {
        int o = o0 + ty * 4 + r;
        float s = (o < DH) ? SCALE : 1.0f;
        float4 v = make_float4(acc[r][0] * s, acc[r][1] * s, acc[r][2] * s, acc[r][3] * s);
        *(float4*)(g_QK + ((size_t)b * NO + o) * HW + n0 + tx * 4) = v;
    }
}

// ---------------------------------------------------------------------------
// Kernel 2: fused sim + softmax.
// Block = 64 query rows x all 4096 keys, two passes (stats, then write).
// smem: Qt[128][64] + Kt[128][64] = 64 KB dynamic.
// ---------------------------------------------------------------------------
extern __shared__ float sm_attn[];

__global__ __launch_bounds__(256) void attn_kernel(float* __restrict__ out) {
    float (*Qt)[64] = (float (*)[64])sm_attn;                  // [d][n]
    float (*Kt)[64] = (float (*)[64])(sm_attn + 128 * 64);     // [d][m]
    const int n0 = blockIdx.x * 64;
    const int b  = blockIdx.y;
    const int tid = threadIdx.x;
    const int tx = tid & 15;
    const int ty = tid >> 4;
    const float* Qb = g_QK + (size_t)b * NO * HW;   // [d][n]
    const float* Kb = Qb + (size_t)DH * HW;         // [d][m]

    // Load Q tile once (k-major source layout, no transpose needed)
    #pragma unroll
    for (int i = 0; i < 8; i++) {
        int f = tid + i * 256;
        int row = f >> 4;
        int c4  = f & 15;
        *(float4*)&Qt[row][c4 * 4] =
            *(const float4*)(Qb + (size_t)row * HW + n0 + c4 * 4);
    }

    float M[4], L[4], invL[4];
    #pragma unroll
    for (int r = 0; r < 4; r++) { M[r] = -1e30f; L[r] = 0.0f; }

    for (int pass = 0; pass < 2; pass++) {
        if (pass == 1) {
            #pragma unroll
            for (int r = 0; r < 4; r++) invL[r] = 1.0f / L[r];
        }
        for (int mt = 0; mt < 64; mt++) {
            __syncthreads();
            #pragma unroll
            for (int i = 0; i < 8; i++) {
                int f = tid + i * 256;
                int row = f >> 4;
                int c4  = f & 15;
                *(float4*)&Kt[row][c4 * 4] =
                    *(const float4*)(Kb + (size_t)row * HW + mt * 64 + c4 * 4);
            }
            __syncthreads();

            float S[4][4] = {};
            #pragma unroll 8
            for (int k = 0; k < 128; k++) {
                float a[4], bb[4];
                *(float4*)a  = *(const float4*)&Qt[k][ty * 4];
                *(float4*)bb = *(const float4*)&Kt[k][tx * 4];
                #pragma unroll
                for (int r = 0; r < 4; r++)
                    #pragma unroll
                    for (int c = 0; c < 4; c++)
                        S[r][c] = fmaf(a[r], bb[c], S[r][c]);
            }

            if (pass == 0) {
                // Online row max + expsum; reduce across the 16 tx threads
                // (xor 1..8 stays inside each 16-lane half-warp).
                #pragma unroll
                for (int r = 0; r < 4; r++) {
                    float tmax = fmaxf(fmaxf(S[r][0], S[r][1]), fmaxf(S[r][2], S[r][3]));
                    #pragma unroll
                    for (int off = 1; off < 16; off <<= 1)
                        tmax = fmaxf(tmax, __shfl_xor_sync(0xffffffffu, tmax, off));
                    float newM = fmaxf(M[r], tmax);
                    float psum = __expf(S[r][0] - newM) + __expf(S[r][1] - newM)
                               + __expf(S[r][2] - newM) + __expf(S[r][3] - newM);
                    #pragma unroll
                    for (int off = 1; off < 16; off <<= 1)
                        psum += __shfl_xor_sync(0xffffffffu, psum, off);
                    L[r] = L[r] * __expf(M[r] - newM) + psum;
                    M[r] = newM;
                }
            } else {
                #pragma unroll
                for (int r = 0; r < 4; r++) {
                    float4 v;
                    v.x = __expf(S[r][0] - M[r]) * invL[r];
                    v.y = __expf(S[r][1] - M[r]) * invL[r];
                    v.z = __expf(S[r][2] - M[r]) * invL[r];
                    v.w = __expf(S[r][3] - M[r]) * invL[r];
                    size_t n = (size_t)b * HW + n0 + ty * 4 + r;
                    *(float4*)(out + n * (size_t)HW + mt * 64 + tx * 4) = v;
                }
            }
        }
    }
}

extern "C" void kernel_launch(void* const* d_in, const int* in_sizes, int n_in,
                              void* d_out, int out_size) {
    (void)in_sizes; (void)n_in; (void)out_size;
    const float* x = (const float*)d_in[0];   // (8, 256, 64, 64) fp32
    const float* W = (const float*)d_in[1];   // (256, 256) fp32
    float* out = (float*)d_out;               // (8, 1, 4096, 4096) fp32

    proj_kernel<<<dim3(HW / 64, NO / 64, NB), 256>>>(x, W);

    cudaFuncSetAttribute(attn_kernel,
                         cudaFuncAttributeMaxDynamicSharedMemorySize, 64 * 1024);
    attn_kernel<<<dim3(HW / 64, NB), 256, 64 * 1024>>>(out);
}

// round 5
// speedup vs baseline: 2.9850x; 2.9850x over previous
#include <cuda_runtime.h>
#include <cstdint>

#define NB 8
#define NC 256
#define HW 4096
#define DH 128
#define NO 256

#define QTILE 128        // queries per block
#define KTILE 64         // keys per smem tile
#define NKT (HW / KTILE) // 64 key tiles
#define STRD 132         // padded floats per smem row (conflict-free)

// Scratch: projected q (pre-scaled) and k, layout [b][token][d], d contiguous,
// values pre-rounded to tf32 (RNA) so mma.sync tf32 sees exact operands.
__device__ float g_Q[(size_t)NB * HW * DH];
__device__ float g_K[(size_t)NB * HW * DH];

__device__ __forceinline__ float tf32_rna(float x) {
    uint32_t u;
    asm("cvt.rna.tf32.f32 %0, %1;" : "=r"(u) : "f"(x));
    return __uint_as_float(u);
}

__device__ __forceinline__ void mma_tf32(float c[4], const uint32_t a[4],
                                         const uint32_t b[2]) {
    asm volatile(
        "mma.sync.aligned.m16n8k8.row.col.f32.tf32.tf32.f32 "
        "{%0,%1,%2,%3}, {%4,%5,%6,%7}, {%8,%9}, {%0,%1,%2,%3};"
        : "+f"(c[0]), "+f"(c[1]), "+f"(c[2]), "+f"(c[3])
        : "r"(a[0]), "r"(a[1]), "r"(a[2]), "r"(a[3]), "r"(b[0]), "r"(b[1]));
}

// ---------------------------------------------------------------------------
// Kernel 1: projection.  g_Q[b][n][o] / g_K[b][n][o-128] = sum_c W[o][c]*x[b][c][n]
// q rows pre-scaled by 128^-0.5; outputs rounded to tf32 (RNA).
// ---------------------------------------------------------------------------
__global__ __launch_bounds__(256) void proj_kernel(const float* __restrict__ x,
                                                   const float* __restrict__ W) {
    __shared__ float As[32][64];   // [k][o]
    __shared__ float Bs[32][64];   // [k][n]
    const int n0 = blockIdx.x * 64;
    const int o0 = blockIdx.y * 64;
    const int b  = blockIdx.z;
    const int tid = threadIdx.x;
    const int tx = tid & 15;
    const int ty = tid >> 4;
    const float* xb = x + (size_t)b * NC * HW;

    float acc[4][4] = {};
    for (int k0 = 0; k0 < NC; k0 += 32) {
        __syncthreads();
        #pragma unroll
        for (int i = 0; i < 2; i++) {
            int f = tid + i * 256;
            int row = f >> 3;
            int c4  = f & 7;
            float4 v = *(const float4*)(W + (size_t)(o0 + row) * NC + k0 + c4 * 4);
            As[c4 * 4 + 0][row] = v.x;
            As[c4 * 4 + 1][row] = v.y;
            As[c4 * 4 + 2][row] = v.z;
            As[c4 * 4 + 3][row] = v.w;
        }
        #pragma unroll
        for (int i = 0; i < 2; i++) {
            int f = tid + i * 256;
            int row = f >> 4;
            int c4  = f & 15;
            *(float4*)&Bs[row][c4 * 4] =
                *(const float4*)(xb + (size_t)(k0 + row) * HW + n0 + c4 * 4);
        }
        __syncthreads();
        #pragma unroll
        for (int k = 0; k < 32; k++) {
            float a[4], bb[4];
            *(float4*)a  = *(const float4*)&As[k][ty * 4];
            *(float4*)bb = *(const float4*)&Bs[k][tx * 4];
            #pragma unroll
            for (int r = 0; r < 4; r++)
                #pragma unroll
                for (int c = 0; c < 4; c++)
                    acc[r][c] = fmaf(a[r], bb[c], acc[r][c]);
        }
    }
    const float SCALE = 0.088388347648318447f;  // 128^-0.5
    const bool is_q = (o0 < DH);
    const float s = is_q ? SCALE : 1.0f;
    float* dst = is_q ? g_Q : g_K;
    const int od = is_q ? o0 : (o0 - DH);
    #pragma unroll
    for (int c = 0; c < 4; c++) {
        int n = n0 + tx * 4 + c;
        float4 v;
        v.x = tf32_rna(acc[0][c] * s);
        v.y = tf32_rna(acc[1][c] * s);
        v.z = tf32_rna(acc[2][c] * s);
        v.w = tf32_rna(acc[3][c] * s);
        *(float4*)(dst + ((size_t)b * HW + n) * DH + od + ty * 4) = v;
    }
}

// ---------------------------------------------------------------------------
// Kernel 2: fused sim + softmax via mma.sync tf32 (m16n8k8).
// Block: 128 queries x all keys in 64-key tiles; 8 warps in 4(m) x 2(n) grid.
// Warp tile 32x32 = 2 mfrags x 4 nfrags. Two passes: expsum, then write.
// Cross-warp L reduction via LRed[128][2] (warps 2j / 2j+1 share rows but
// cover different key columns).
// smem: Q[128][132] + K[64][132] + LRed = 100 KB -> 2 blocks/SM.
// ---------------------------------------------------------------------------
extern __shared__ float smx[];

__global__ __launch_bounds__(256, 2) void attn_kernel(float* __restrict__ out) {
    float* Qs = smx;                                  // [128][STRD]
    float* Ks = smx + QTILE * STRD;                   // [64][STRD]
    float* LRed = smx + (QTILE + KTILE) * STRD;       // [128][2]

    const int q0 = blockIdx.x * QTILE;
    const int b  = blockIdx.y;
    const int tid = threadIdx.x;
    const int wid = tid >> 5;
    const int lane = tid & 31;
    const int gid = lane >> 2;
    const int tid4 = lane & 3;

    const int wm0 = (wid >> 1) * 32;    // warp m offset (0,32,64,96)
    const int wn0 = (wid & 1) * 32;     // warp n offset within key tile (0,32)

    // Load Q tile (128 rows x 128 d) into padded smem.
    {
        const float* Qg = g_Q + ((size_t)b * HW + q0) * DH;
        #pragma unroll
        for (int i = 0; i < 16; i++) {
            int f = tid + i * 256;       // 4096 float4
            int row = f >> 5;
            int c4  = f & 31;
            *(float4*)&Qs[row * STRD + c4 * 4] =
                *(const float4*)(Qg + (size_t)row * DH + c4 * 4);
        }
    }
    const float* Kg = g_K + (size_t)b * HW * DH;

    // Fragment smem base addresses (conflict-free: bank = 4*gid + tid4 + k).
    const float* Ab = Qs + (wm0 + gid) * STRD + tid4;
    const float* Bb = Ks + (wn0 + gid) * STRD + tid4;

    float Lp[2][2] = {};   // expsum partials (this warp's key cols): [mfrag][row-half]
    float iL[2][2];

    for (int pass = 0; pass < 2; pass++) {
        if (pass == 1) {
            // Quad-reduce Lp (lanes sharing gid), publish per (row, n-half),
            // then combine the two warp halves for the full row sum.
            #pragma unroll
            for (int mf = 0; mf < 2; mf++)
                #pragma unroll
                for (int h = 0; h < 2; h++) {
                    float v = Lp[mf][h];
                    v += __shfl_xor_sync(0xffffffffu, v, 1);
                    v += __shfl_xor_sync(0xffffffffu, v, 2);
                    if (tid4 == 0)
                        LRed[(wm0 + mf * 16 + h * 8 + gid) * 2 + (wid & 1)] = v;
                }
            __syncthreads();
            #pragma unroll
            for (int mf = 0; mf < 2; mf++)
                #pragma unroll
                for (int h = 0; h < 2; h++) {
                    int row = wm0 + mf * 16 + h * 8 + gid;
                    iL[mf][h] = 1.0f / (LRed[row * 2] + LRed[row * 2 + 1]);
                }
        }
        for (int kt = 0; kt < NKT; kt++) {
            __syncthreads();   // everyone done with previous Ks
            #pragma unroll
            for (int i = 0; i < 8; i++) {
                int f = tid + i * 256;   // 2048 float4
                int row = f >> 5;
                int c4  = f & 31;
                *(float4*)&Ks[row * STRD + c4 * 4] =
                    *(const float4*)(Kg + (size_t)(kt * KTILE + row) * DH + c4 * 4);
            }
            __syncthreads();

            float acc[2][4][4] = {};
            #pragma unroll
            for (int ks = 0; ks < 16; ks++) {
                const int k = ks * 8;
                uint32_t a[2][4], bf[4][2];
                #pragma unroll
                for (int mf = 0; mf < 2; mf++) {
                    const float* p = Ab + mf * 16 * STRD + k;
                    a[mf][0] = __float_as_uint(p[0]);
                    a[mf][1] = __float_as_uint(p[8 * STRD]);
                    a[mf][2] = __float_as_uint(p[4]);
                    a[mf][3] = __float_as_uint(p[8 * STRD + 4]);
                }
                #pragma unroll
                for (int nf = 0; nf < 4; nf++) {
                    const float* p = Bb + nf * 8 * STRD + k;
                    bf[nf][0] = __float_as_uint(p[0]);
                    bf[nf][1] = __float_as_uint(p[4]);
                }
                #pragma unroll
                for (int mf = 0; mf < 2; mf++)
                    #pragma unroll
                    for (int nf = 0; nf < 4; nf++)
                        mma_tf32(acc[mf][nf], a[mf], bf[nf]);
            }

            if (pass == 0) {
                #pragma unroll
                for (int mf = 0; mf < 2; mf++) {
                    float s0 = 0.0f, s1 = 0.0f;
                    #pragma unroll
                    for (int nf = 0; nf < 4; nf++) {
                        s0 += __expf(acc[mf][nf][0]) + __expf(acc[mf][nf][1]);
                        s1 += __expf(acc[mf][nf][2]) + __expf(acc[mf][nf][3]);
                    }
                    Lp[mf][0] += s0;
                    Lp[mf][1] += s1;
                }
            } else {
                #pragma unroll
                for (int mf = 0; mf < 2; mf++) {
                    const int row = q0 + wm0 + mf * 16 + gid;
                    float* o0p = out + ((size_t)b * HW + row) * HW + kt * KTILE + wn0 + tid4 * 2;
                    float* o1p = o0p + 8 * (size_t)HW;
                    #pragma unroll
                    for (int nf = 0; nf < 4; nf++) {
                        float2 v0, v1;
                        v0.x = __expf(acc[mf][nf][0]) * iL[mf][0];
                        v0.y = __expf(acc[mf][nf][1]) * iL[mf][0];
                        v1.x = __expf(acc[mf][nf][2]) * iL[mf][1];
                        v1.y = __expf(acc[mf][nf][3]) * iL[mf][1];
                        *(float2*)(o0p + nf * 8) = v0;
                        *(float2*)(o1p + nf * 8) = v1;
                    }
                }
            }
        }
    }
}

extern "C" void kernel_launch(void* const* d_in, const int* in_sizes, int n_in,
                              void* d_out, int out_size) {
    (void)in_sizes; (void)n_in; (void)out_size;
    const float* x = (const float*)d_in[0];   // (8, 256, 64, 64) fp32
    const float* W = (const float*)d_in[1];   // (256, 256) fp32
    float* out = (float*)d_out;               // (8, 1, 4096, 4096) fp32

    proj_kernel<<<dim3(HW / 64, NO / 64, NB), 256>>>(x, W);

    const int smem = (QTILE + KTILE) * STRD * sizeof(float) + QTILE * 2 * sizeof(float);
    cudaFuncSetAttribute(attn_kernel,
                         cudaFuncAttributeMaxDynamicSharedMemorySize, smem);
    attn_kernel<<<dim3(HW / QTILE, NB), 256, smem>>>(out);
}